// round 7
// baseline (speedup 1.0000x reference)
#include <cuda_runtime.h>

// Inputs (metadata order): z [8192*128] f32 (UNUSED), risk [B] f32, time [B] f32, event [B] i32.
// Output: single f32 scalar = mean hinge over pairs (time[i] < time[j] && event[i]==1).
//
// Single persistent kernel, 296 blocks (2/SM, all resident -> software grid barriers OK):
//   A1: parallel histogram of time-buckets (64) for all rows (j) and event rows (i);
//       block 0 also re-inits per-chunk min/max range arrays.
//   A2: block 0 turns counts into base cursors (exclusive prefix), publishes ni.
//   A3: parallel scatter into bucketed arrays g_j / g_i via atomic cursors; per-chunk
//       time ranges tracked with atomicMin/Max on float bits (times >= 0).
//   B : persistent tile loop over (i-chunk 512) x (j-chunk 256). Classification via
//       precomputed ranges: skip (no pair fires) / free (all fire: 3-op body +
//       closed-form count) / mixed (exact per-pair strict predicate).
//   C : global double/u64 accumulation; last block finalizes and resets globals
//       (replay-idempotent for CUDA-graph replay).

#define B_CAP  8192
#define NB     64
#define TPB    256
#define NBLK   296                      // 148 SMs * 2 blocks
#define ICH    512
#define JCH    256
#define NJC_MAX ((B_CAP + JCH - 1) / JCH)   // 32
#define NIC_MAX ((B_CAP + ICH - 1) / ICH)   // 16
#define PINF_BITS 0x7f800000
#define NINF_BITS 0xff800000

__device__ float2             g_j[B_CAP];      // (risk, time), time-bucketed
__device__ float2             g_i[B_CAP];      // (risk+1, time), event rows, bucketed
__device__ int                g_histJ[NB];     // counts -> cursors (in-place)
__device__ int                g_histI[NB];
__device__ int                g_jmin[NJC_MAX], g_jmax[NJC_MAX];   // float bits
__device__ int                g_imin[NIC_MAX], g_imax[NIC_MAX];
__device__ int                g_ni;
__device__ unsigned int       g_bar;
__device__ double             g_total;
__device__ unsigned long long g_cnt;
__device__ unsigned int       g_done;

__device__ __forceinline__ void grid_barrier(unsigned int target) {
    __syncthreads();
    if (threadIdx.x == 0) {
        __threadfence();
        atomicAdd(&g_bar, 1u);
        while (*(volatile unsigned int*)&g_bar < target) { }
        __threadfence();
    }
    __syncthreads();
}

__global__ __launch_bounds__(TPB, 2) void k_all(const float* __restrict__ risk,
                                                const float* __restrict__ time_,
                                                const int*   __restrict__ event,
                                                float*       __restrict__ out,
                                                int n) {
    __shared__ float2 sj[JCH];          // (risk_j, time_j)  (pads: time = +/-inf floats)
    __shared__ float  swsum[TPB / 32];
    __shared__ int    swcnt[TPB / 32];

    const int tid    = threadIdx.x;
    const int lane   = tid & 31;
    const int w      = tid >> 5;
    const int bid    = blockIdx.x;
    const int nblk   = gridDim.x;
    const unsigned stride = nblk * TPB;

    // ================= Phase A1: histogram (+ range-array init by block 0) ==========
    if (bid == 0) {
        if (tid < NJC_MAX)            { g_jmin[tid] = PINF_BITS; g_jmax[tid] = NINF_BITS; }
        if (tid >= 32 && tid < 32 + NIC_MAX) { g_imin[tid - 32] = PINF_BITS; g_imax[tid - 32] = NINF_BITS; }
    }
    for (unsigned r = bid * TPB + tid; r < (unsigned)n; r += stride) {
        float t = time_[r];
        int b = (int)(t * (float)NB);
        b = b < 0 ? 0 : (b > NB - 1 ? NB - 1 : b);
        atomicAdd(&g_histJ[b], 1);
        if (event[r] == 1) atomicAdd(&g_histI[b], 1);
    }
    grid_barrier(1u * nblk);

    // ================= Phase A2: block 0 prefix (counts -> base cursors) ============
    if (bid == 0 && tid == 0) {
        int aj = 0, ai = 0;
        #pragma unroll
        for (int b = 0; b < NB; b++) {
            int cj = g_histJ[b], ci = g_histI[b];
            g_histJ[b] = aj; g_histI[b] = ai;
            aj += cj; ai += ci;
        }
        g_ni = ai;
    }
    grid_barrier(2u * nblk);

    // ================= Phase A3: scatter + per-chunk time ranges ====================
    for (unsigned r = bid * TPB + tid; r < (unsigned)n; r += stride) {
        float t  = time_[r];
        float rk = risk[r];
        int   tb = __float_as_int(t);      // t >= 0 -> int-monotone
        int b = (int)(t * (float)NB);
        b = b < 0 ? 0 : (b > NB - 1 ? NB - 1 : b);
        int d = atomicAdd(&g_histJ[b], 1);
        g_j[d] = make_float2(rk, t);
        atomicMin(&g_jmin[d / JCH], tb);
        atomicMax(&g_jmax[d / JCH], tb);
        if (event[r] == 1) {
            int di = atomicAdd(&g_histI[b], 1);
            g_i[di] = make_float2(rk + 1.0f, t);
            atomicMin(&g_imin[di / ICH], tb);
            atomicMax(&g_imax[di / ICH], tb);
        }
    }
    grid_barrier(3u * nblk);

    // ================= Phase B: persistent classified tile loop =====================
    const int ni  = g_ni;
    const int njc = (n  + JCH - 1) / JCH;
    const int nic = (ni + ICH - 1) / ICH;
    const int ntiles = nic * njc;

    float              s_acc   = 0.0f;
    int                c_mixed = 0;
    unsigned long long c_free  = 0ull;   // thread 0 only

    for (int tile = bid; tile < ntiles; tile += nblk) {
        const int ic = tile / njc;
        const int jc = tile - ic * njc;

        // classification from precomputed ranges (int compares on float bits)
        const int jmn = g_jmin[jc], jmx = g_jmax[jc];
        const int imn = g_imin[ic], imx = g_imax[ic];
        if (jmx <= imn) continue;                      // skip: no pair can fire
        const bool isfree = (jmn > imx);               // all pairs fire (strict)

        __syncthreads();                               // protect sj from prev tile
        {   // load j-chunk
            int j = jc * JCH + tid;
            float rj = __int_as_float(PINF_BITS);      // pad: hinge contributes 0
            float tj = __int_as_float(NINF_BITS);      // pad: predicate never true
            if (j < n) { float2 v = g_j[j]; rj = v.x; tj = v.y; }
            sj[tid] = make_float2(rj, tj);
        }
        // load 2 i's into registers
        const int i0 = ic * ICH;
        float r0 = __int_as_float(NINF_BITS), r1 = r0; // pad: hinge contributes 0
        int   t0b = PINF_BITS, t1b = PINF_BITS;        // pad: predicate never true
        if (i0 + tid < ni)       { float2 u = g_i[i0 + tid];       r0 = u.x; t0b = __float_as_int(u.y); }
        if (i0 + TPB + tid < ni) { float2 u = g_i[i0 + TPB + tid]; r1 = u.x; t1b = __float_as_int(u.y); }
        __syncthreads();

        if (isfree) {
            float s0 = 0.f, s1 = 0.f;
            #pragma unroll 8
            for (int k = 0; k < JCH; k++) {
                float rj = sj[k].x;
                s0 += fmaxf(r0 - rj, 0.0f);
                s1 += fmaxf(r1 - rj, 0.0f);
            }
            s_acc += s0 + s1;
            if (tid == 0) {
                unsigned long long nib = (unsigned long long)min(ni - i0, ICH);
                unsigned long long njb = (unsigned long long)min(n - jc * JCH, JCH);
                c_free += nib * njb;
            }
        } else {
            float s0 = 0.f, s1 = 0.f;
            int   c0 = 0,   c1 = 0;
            #pragma unroll 8
            for (int k = 0; k < JCH; k++) {
                float2 v  = sj[k];
                int   tjb = __float_as_int(v.y);
                float h0  = fmaxf(r0 - v.x, 0.0f);
                float h1  = fmaxf(r1 - v.x, 0.0f);
                bool  p0  = tjb > t0b;
                bool  p1  = tjb > t1b;
                s0 += p0 ? h0 : 0.0f;
                s1 += p1 ? h1 : 0.0f;
                c0 += (int)p0;
                c1 += (int)p1;
            }
            s_acc   += s0 + s1;
            c_mixed += c0 + c1;
        }
    }

    // ================= Phase C: reduce + finalize ===================================
    #pragma unroll
    for (int off = 16; off >= 1; off >>= 1) {
        s_acc   += __shfl_down_sync(0xffffffffu, s_acc, off);
        c_mixed += __shfl_down_sync(0xffffffffu, c_mixed, off);
    }
    if (lane == 0) { swsum[w] = s_acc; swcnt[w] = c_mixed; }
    __syncthreads();
    if (tid == 0) {
        float s = 0.f; long long c = 0;
        #pragma unroll
        for (int q = 0; q < TPB / 32; q++) { s += swsum[q]; c += swcnt[q]; }
        unsigned long long cll = (unsigned long long)c + c_free;
        if (s != 0.0f)   atomicAdd(&g_total, (double)s);
        if (cll != 0ull) atomicAdd(&g_cnt, cll);
        __threadfence();
        unsigned int prev = atomicAdd(&g_done, 1u);
        if (prev == (unsigned int)nblk - 1u) {
            __threadfence();
            double tt = *(volatile double*)&g_total;
            unsigned long long cc = *(volatile unsigned long long*)&g_cnt;
            out[0] = (cc == 0ull) ? 0.0f : (float)(tt / (double)cc);
            // reset everything for the next graph replay
            #pragma unroll
            for (int b = 0; b < NB; b++) { g_histJ[b] = 0; g_histI[b] = 0; }
            g_total = 0.0;
            g_cnt   = 0ull;
            g_bar   = 0u;
            g_done  = 0u;
        }
    }
}

extern "C" void kernel_launch(void* const* d_in, const int* in_sizes, int n_in,
                              void* d_out, int out_size) {
    const float* risk  = (const float*)d_in[1];
    const float* time_ = (const float*)d_in[2];
    const int*   event = (const int*)d_in[3];
    const int n = in_sizes[1];

    k_all<<<NBLK, TPB>>>(risk, time_, event, (float*)d_out, n);
}

// round 8
// speedup vs baseline: 1.8199x; 1.8199x over previous
#include <cuda_runtime.h>

// Inputs (metadata order): z [8192*128] f32 (UNUSED), risk [B] f32, time [B] f32, event [B] i32.
// Output: single f32 scalar = mean hinge over pairs (time[i] < time[j] && event[i]==1).
//
// K1: scatter rows into 32 time-buckets (all rows -> g_J; event rows -> g_I, risk+1).
// K2: tile grid over (bi, bj) bucket pairs:
//       bj <  bi : skip   (tj < ti guaranteed)
//       bj >  bi : FREE   (ti < tj guaranteed strictly) -> 3-op body, closed-form count
//       bj == bi : MIXED  (exact per-pair strict compare)
//     Double/u64 global accumulation; last block finalizes AND resets cursors/globals
//     so the launch sequence is idempotent under CUDA-graph replay.

#define NB    32
#define CAP   8192
#define TPB   256
#define JT    256
#define NBLK2 (NB * NB)

__device__ float2             g_J[NB * CAP];   // (risk, time) per time-bucket
__device__ float2             g_I[NB * CAP];   // (risk+1, time), event rows only
__device__ int                g_cJ[NB];        // bucket counts (zeroed at load / by finalize)
__device__ int                g_cI[NB];
__device__ double             g_total;
__device__ unsigned long long g_cnt;
__device__ unsigned int       g_done;

// ---------------- K1: bucket scatter ----------------
__global__ void k_scatter(const float* __restrict__ risk,
                          const float* __restrict__ time_,
                          const int*   __restrict__ event,
                          int n) {
    int r = blockIdx.x * blockDim.x + threadIdx.x;
    if (r >= n) return;
    float t  = time_[r];
    float rk = risk[r];
    int b = (int)(t * (float)NB);
    b = b < 0 ? 0 : (b > NB - 1 ? NB - 1 : b);
    int d = atomicAdd(&g_cJ[b], 1);
    g_J[b * CAP + d] = make_float2(rk, t);
    if (event[r] == 1) {
        int di = atomicAdd(&g_cI[b], 1);
        g_I[b * CAP + di] = make_float2(rk + 1.0f, t);
    }
}

// ---------------- K2: classified bucket-tile loop ----------------
__global__ __launch_bounds__(TPB) void k_tiles(float* __restrict__ out) {
    __shared__ float sjr[JT];          // risk_j
    __shared__ int   sjt[JT];          // time_j bits (times >= 0, or -inf pad)
    __shared__ float swsum[TPB / 32];
    __shared__ int   swcnt[TPB / 32];

    const int tid  = threadIdx.x;
    const int lane = tid & 31;
    const int w    = tid >> 5;
    const int bi   = blockIdx.x;
    const int bj   = blockIdx.y;

    float              s  = 0.0f;
    int                c  = 0;
    unsigned long long cf = 0ull;      // thread 0 only

    if (bj >= bi) {
        const int ni = g_cI[bi];
        const int nj = g_cJ[bj];
        if (ni > 0 && nj > 0) {
            const bool freeT = (bj > bi);
            if (freeT && tid == 0)
                cf = (unsigned long long)ni * (unsigned long long)nj;

            const float2* __restrict__ I = g_I + bi * CAP;
            const float2* __restrict__ J = g_J + bj * CAP;

            for (int i0 = 0; i0 < ni; i0 += 2 * TPB) {
                const int  ia  = i0 + 2 * tid;        // consecutive pair of i's
                const bool act = (ia < ni);           // inert threads skip inner loops
                float r0 = __int_as_float(0xff800000);   // -inf: hinge contributes 0
                float r1 = r0;
                int   t0b = 0x7f800000, t1b = 0x7f800000; // +inf bits: pred never true
                if (act) {
                    float2 u = I[ia];
                    r0 = u.x; t0b = __float_as_int(u.y);
                    if (ia + 1 < ni) { float2 v = I[ia + 1]; r1 = v.x; t1b = __float_as_int(v.y); }
                }

                float s0 = 0.f, s1 = 0.f;
                int   c0 = 0,   c1 = 0;

                for (int j0 = 0; j0 < nj; j0 += JT) {
                    __syncthreads();
                    {
                        int k = j0 + tid;
                        float rj  = __int_as_float(0x7f800000);  // +inf pad: free body adds 0
                        int   tjb = 0xff800000;                  // -inf pad: mixed pred false
                        if (k < nj) { float2 v = J[k]; rj = v.x; tjb = __float_as_int(v.y); }
                        sjr[tid] = rj;
                        sjt[tid] = tjb;
                    }
                    __syncthreads();

                    if (act) {
                        if (freeT) {
                            #pragma unroll 8
                            for (int k = 0; k < JT; k++) {
                                float rj = sjr[k];
                                s0 += fmaxf(r0 - rj, 0.0f);
                                s1 += fmaxf(r1 - rj, 0.0f);
                            }
                        } else {
                            #pragma unroll 8
                            for (int k = 0; k < JT; k++) {
                                float rj  = sjr[k];
                                int   tjb = sjt[k];
                                bool  p0  = tjb > t0b;
                                bool  p1  = tjb > t1b;
                                s0 += p0 ? fmaxf(r0 - rj, 0.0f) : 0.0f;
                                s1 += p1 ? fmaxf(r1 - rj, 0.0f) : 0.0f;
                                c0 += (int)p0;
                                c1 += (int)p1;
                            }
                        }
                    }
                }
                s += s0 + s1;
                c += c0 + c1;
            }
        }
    }

    // ---- reduce + global accumulate + finalize ----
    #pragma unroll
    for (int off = 16; off >= 1; off >>= 1) {
        s += __shfl_down_sync(0xffffffffu, s, off);
        c += __shfl_down_sync(0xffffffffu, c, off);
    }
    if (lane == 0) { swsum[w] = s; swcnt[w] = c; }
    __syncthreads();
    if (tid == 0) {
        float ss = 0.f; int cc = 0;
        #pragma unroll
        for (int q = 0; q < TPB / 32; q++) { ss += swsum[q]; cc += swcnt[q]; }
        unsigned long long ctot = (unsigned long long)cc + cf;
        if (ss != 0.0f)  atomicAdd(&g_total, (double)ss);
        if (ctot != 0ull) atomicAdd(&g_cnt, ctot);
        __threadfence();
        unsigned int prev = atomicAdd(&g_done, 1u);
        if (prev == (unsigned int)NBLK2 - 1u) {
            __threadfence();
            double tt = *(volatile double*)&g_total;
            unsigned long long cn = *(volatile unsigned long long*)&g_cnt;
            out[0] = (cn != 0ull) ? (float)(tt / (double)cn) : 0.0f;
            // reset all state: launch sequence idempotent for next graph replay
            #pragma unroll
            for (int b = 0; b < NB; b++) { g_cJ[b] = 0; g_cI[b] = 0; }
            g_total = 0.0;
            g_cnt   = 0ull;
            g_done  = 0u;
        }
    }
}

extern "C" void kernel_launch(void* const* d_in, const int* in_sizes, int n_in,
                              void* d_out, int out_size) {
    const float* risk  = (const float*)d_in[1];
    const float* time_ = (const float*)d_in[2];
    const int*   event = (const int*)d_in[3];
    const int n = in_sizes[1];

    k_scatter<<<(n + TPB - 1) / TPB, TPB>>>(risk, time_, event, n);

    dim3 g2(NB, NB);
    k_tiles<<<g2, TPB>>>((float*)d_out);
}